// round 16
// baseline (speedup 1.0000x reference)
#include <cuda_runtime.h>
#include <cuda_fp16.h>
#include <cstdint>

#define M_V 50000   // vocab
#define N_F 1000    // filters
#define K_D 300     // embedding dim
#define B_B 128
#define L_L 512

#define MP 50048    // padded A rows (391*128)
#define NP 1024     // padded B rows (8*128)
#define KPAIR 160   // K in half-pairs: 320 halves = 10 chunks x 32
#define KU4 80      // uint4 per row

#define SCALE_IN  128.0f              // 2^7 per operand (keeps lo normal-range)
#define SCALE_OUT (1.0f / 16384.0f)   // 2^-14 on scores

// scratch — referenced ONLY from device code (never as host-side kernel args!)
__device__ float g_S[(size_t)M_V * N_F];        // 200 MB (scaled by 2^14)
__device__ uint2 g_A2[(size_t)MP * KPAIR];      // 64 MB pre-split (h2,l2)
__device__ uint2 g_B2[(size_t)NP * KPAIR];      // 1.3 MB

#define LDP 12                    // uint2 row stride (8 pairs + 4 pad) - proven
#define SUB_U2 (256 * LDP)        // one BK=16 sub-tile (A 0..127, B 128..255)
#define STAGE_U2 (2 * SUB_U2)     // BK=32 stage = 2 stacked sub-tiles
#define SMEM_BYTES (2 * STAGE_U2 * 8)   // 98304
#define NCHUNK 10

// ---------------------------------------------------------------------------
__device__ __forceinline__ uint32_t h2u(half2 h) {
    return *reinterpret_cast<const uint32_t*>(&h);
}

__device__ __forceinline__ void mma16(float* c, const uint32_t* a, const uint32_t* b) {
    asm volatile(
        "mma.sync.aligned.m16n8k16.row.col.f32.f16.f16.f32 "
        "{%0,%1,%2,%3}, {%4,%5,%6,%7}, {%8,%9}, {%0,%1,%2,%3};"
        : "+f"(c[0]), "+f"(c[1]), "+f"(c[2]), "+f"(c[3])
        : "r"(a[0]), "r"(a[1]), "r"(a[2]), "r"(a[3]), "r"(b[0]), "r"(b[1]));
}

#define CP16(sm_u32, gp) \
    asm volatile("cp.async.cg.shared.global [%0], [%1], 16;" :: "r"(sm_u32), "l"(gp))
#define CP_COMMIT() asm volatile("cp.async.commit_group;" ::: "memory")
#define CP_WAIT0()  asm volatile("cp.async.wait_group 0;" ::: "memory")

// split 4 floats (scaled 2^7) into two (hi2, lo2) uint2 pairs
__device__ __forceinline__ uint4 split4(float4 v) {
    float x0 = v.x * SCALE_IN, x1 = v.y * SCALE_IN;
    float x2 = v.z * SCALE_IN, x3 = v.w * SCALE_IN;
    half2 h01 = __floats2half2_rn(x0, x1);
    half2 h23 = __floats2half2_rn(x2, x3);
    float2 f01 = __half22float2(h01);
    float2 f23 = __half22float2(h23);
    half2 l01 = __floats2half2_rn(x0 - f01.x, x1 - f01.y);
    half2 l23 = __floats2half2_rn(x2 - f23.x, x3 - f23.y);
    return make_uint4(h2u(h01), h2u(l01), h2u(h23), h2u(l23));
}

// ===========================================================================
// Presplit: fp32 [rows x 300] -> pair-packed uint2 rows [KPAIR], value *2^7.
// uint2 q = (h2(x2q,x2q+1), l2(x2q,x2q+1)). Row/K padding zeroed.
// ===========================================================================
__global__ __launch_bounds__(256) void presplit_A(const float* __restrict__ src) {
    int idx = blockIdx.x * 256 + threadIdx.x;
    int row = idx / KU4, s = idx - row * KU4;
    if (row >= MP) return;
    float4 v = make_float4(0.f, 0.f, 0.f, 0.f);
    if (row < M_V && s < 75) v = *(const float4*)(src + (size_t)row * K_D + s * 4);
    *(uint4*)(g_A2 + (size_t)row * KPAIR + s * 2) = split4(v);
}

__global__ __launch_bounds__(256) void presplit_B(const float* __restrict__ src) {
    int idx = blockIdx.x * 256 + threadIdx.x;
    int row = idx / KU4, s = idx - row * KU4;
    if (row >= NP) return;
    float4 v = make_float4(0.f, 0.f, 0.f, 0.f);
    if (row < N_F && s < 75) v = *(const float4*)(src + (size_t)row * K_D + s * 4);
    *(uint4*)(g_B2 + (size_t)row * KPAIR + s * 2) = split4(v);
}

// ===========================================================================
// Phase 1: S = Ah.Bh + Ah.Bl + Al.Bh  via fp16 m16n8k16 mma.sync (NT)
// 128x128 CTA tile, BK=32 as TWO stacked BK=16 sub-tiles in the proven
// LDP=12 layout (sub1 at +SUB_U2). 10 chunks, 8 warps (64x32 warptile),
// cp.async staging, 2 CTAs/SM. 96 MMAs per chunk cover one cp.async group
// + one barrier -> copy latency no longer exposed.
// ===========================================================================
__global__ __launch_bounds__(256, 2) void gemm_fp16x3() {
    extern __shared__ uint2 sm[];
    uint32_t smb;
    asm("{ .reg .u64 t; cvta.to.shared.u64 t, %1; cvt.u32.u64 %0, t; }"
        : "=r"(smb) : "l"(sm));

    const int tid = threadIdx.x;
    const int wid = tid >> 5, lid = tid & 31;
    const int qid = lid >> 2, ql = lid & 3;
    const int m0 = blockIdx.y * 128, n0 = blockIdx.x * 128;
    const int wm = (wid >> 2) * 64, wn = (wid & 3) * 32;

    float acc[4][4][4];
#pragma unroll
    for (int mt = 0; mt < 4; mt++)
#pragma unroll
        for (int nt = 0; nt < 4; nt++)
#pragma unroll
            for (int j = 0; j < 4; j++) acc[mt][nt][j] = 0.f;

    // staging: row = tid>>1 (0..127), half = tid&1.
    // Per chunk (8 uint4/row): sub0 = uint4 0..3, sub1 = uint4 4..7;
    // this thread stages uint4 {half*2, half*2+1} of each sub, A and B.
    const int row_st = tid >> 1, half = tid & 1;
    const uint4* gA = (const uint4*)(g_A2 + (size_t)(m0 + row_st) * KPAIR) + half * 2;
    const uint4* gB = (const uint4*)(g_B2 + (size_t)(n0 + row_st) * KPAIR) + half * 2;
    const uint32_t sAb = smb + (uint32_t)(row_st * LDP + half * 4) * 8;
    const uint32_t sBb = sAb + 128 * LDP * 8;

#define ISSUE(c, st) do { \
        uint32_t so = (uint32_t)(st) * (STAGE_U2 * 8); \
        const uint4* ga = gA + (c) * 8; \
        const uint4* gb = gB + (c) * 8; \
        CP16(sAb + so,                 ga);     CP16(sAb + so + 16,                 ga + 1); \
        CP16(sBb + so,                 gb);     CP16(sBb + so + 16,                 gb + 1); \
        CP16(sAb + so + SUB_U2 * 8,    ga + 4); CP16(sAb + so + SUB_U2 * 8 + 16,    ga + 5); \
        CP16(sBb + so + SUB_U2 * 8,    gb + 4); CP16(sBb + so + SUB_U2 * 8 + 16,    gb + 5); \
        CP_COMMIT(); \
    } while (0)

    // ---- prologue: chunk 0 into stage 0 ----
    ISSUE(0, 0);
    CP_WAIT0();
    __syncthreads();

    for (int c = 0; c < NCHUNK; c++) {
        const bool more = (c + 1 < NCHUNK);
        if (more) ISSUE(c + 1, (c + 1) & 1);

#pragma unroll
        for (int kk = 0; kk < 2; kk++) {
            const uint2* As = sm + (c & 1) * STAGE_U2 + kk * SUB_U2;
            const uint2* Bs = As + 128 * LDP;

            uint32_t bh[4][2], bl[4][2];
#pragma unroll
            for (int nt = 0; nt < 4; nt++) {
                const uint2* p = Bs + (wn + nt * 8 + qid) * LDP + ql;
                uint2 b0 = p[0], b1 = p[4];      // pairs ql, ql+4
                bh[nt][0] = b0.x; bh[nt][1] = b1.x;
                bl[nt][0] = b0.y; bl[nt][1] = b1.y;
            }
#pragma unroll
            for (int mt = 0; mt < 4; mt++) {
                const uint2* pa = As + (wm + mt * 16 + qid) * LDP + ql;
                uint2 a0 = pa[0], a1 = pa[8 * LDP];
                uint2 a2 = pa[4], a3 = pa[8 * LDP + 4];
                uint32_t ah[4] = {a0.x, a1.x, a2.x, a3.x};
                uint32_t al[4] = {a0.y, a1.y, a2.y, a3.y};
#pragma unroll
                for (int nt = 0; nt < 4; nt++) {
                    mma16(acc[mt][nt], ah, bh[nt]);   // hi*hi
                    mma16(acc[mt][nt], ah, bl[nt]);   // hi*lo
                    mma16(acc[mt][nt], al, bh[nt]);   // lo*hi
                }
            }
        }

        if (more) {
            CP_WAIT0();       // chunk c+1 landed
            __syncthreads();  // stage (c&1) free; (c+1)&1 visible
        }
    }

    // ---- epilogue (scores scaled by 2^14; phase 2 descales) ----
#pragma unroll
    for (int mt = 0; mt < 4; mt++) {
        int mlo = m0 + wm + mt * 16 + qid;
        int mhi = mlo + 8;
#pragma unroll
        for (int nt = 0; nt < 4; nt++) {
            int n = n0 + wn + nt * 8 + ql * 2;
            if (n < N_F) {
                if (mlo < M_V)
                    *(float2*)(g_S + (size_t)mlo * N_F + n) =
                        make_float2(acc[mt][nt][0], acc[mt][nt][1]);
                if (mhi < M_V)
                    *(float2*)(g_S + (size_t)mhi * N_F + n) =
                        make_float2(acc[mt][nt][2], acc[mt][nt][3]);
            }
        }
    }
}

// ===========================================================================
// Phase 2: per (b,f): first-index argmax over t of S[inp[b,t],f] (scaled:
// argmax invariant); val = relu(2^-14*max + conv_b[f]);
// contrib = val*(fc_w[1,f]-fc_w[0,f]); token[b,argmax] += contrib;
// token += fc_b[1]-fc_b[0]. Deterministic ordered gather.
// ===========================================================================
__global__ __launch_bounds__(1024) void reduce_scatter(
    const int* __restrict__ inp, const float* __restrict__ cb,
    const float* __restrict__ fcw, const float* __restrict__ fcb,
    float* __restrict__ out) {
    __shared__ int   sw[L_L];
    __shared__ int   sbt[N_F];
    __shared__ float sct[N_F];

    const int b = blockIdx.x;
    const int tid = threadIdx.x;

    if (tid < L_L) sw[tid] = inp[b * L_L + tid];
    __syncthreads();

    const int f = tid;
    if (f < N_F) {
        const float* Sf = g_S + f;
        float best = -3.4e38f;
        int bestt = 0;
        for (int t0 = 0; t0 < L_L; t0 += 8) {
            float vv[8];
#pragma unroll
            for (int j = 0; j < 8; j++)
                vv[j] = Sf[(size_t)sw[t0 + j] * N_F];
#pragma unroll
            for (int j = 0; j < 8; j++) {
                if (vv[j] > best) { best = vv[j]; bestt = t0 + j; }  // first idx
            }
        }
        float val = fmaxf(best * SCALE_OUT + cb[f], 0.f);  // descale, relu
        float contrib = val * (fcw[N_F + f] - fcw[f]);     // 0 when val==0
        sbt[f] = bestt;
        sct[f] = contrib;
    }
    __syncthreads();

    if (tid < L_L) {
        float accv = fcb[1] - fcb[0];
        for (int ff = 0; ff < N_F; ff++) {
            if (sbt[ff] == tid) accv += sct[ff];
        }
        out[b * L_L + tid] = accv;
    }
}

extern "C" void kernel_launch(void* const* d_in, const int* in_sizes, int n_in,
                              void* d_out, int out_size) {
    const int*   inp    = (const int*)d_in[0];
    const float* emb    = (const float*)d_in[1];
    const float* conv_w = (const float*)d_in[2];   // [1000,1,300] contiguous
    const float* conv_b = (const float*)d_in[3];
    const float* fc_w   = (const float*)d_in[4];   // [2,1000]
    const float* fc_b   = (const float*)d_in[5];
    float* out = (float*)d_out;

    static int smem_set = 0;
    if (!smem_set) {
        cudaFuncSetAttribute(gemm_fp16x3,
                             cudaFuncAttributeMaxDynamicSharedMemorySize,
                             SMEM_BYTES);
        smem_set = 1;
    }

    presplit_A<<<(MP * KU4 + 255) / 256, 256>>>(emb);
    presplit_B<<<(NP * KU4 + 255) / 256, 256>>>(conv_w);
    gemm_fp16x3<<<dim3(8, 391), 256, SMEM_BYTES>>>();
    reduce_scatter<<<B_B, 1024>>>(inp, conv_b, fc_w, fc_b, out);
}

// round 17
// speedup vs baseline: 1.0827x; 1.0827x over previous
#include <cuda_runtime.h>
#include <cuda_fp16.h>
#include <cstdint>

#define M_V 50000   // vocab
#define N_F 1000    // filters
#define K_D 300     // embedding dim
#define B_B 128
#define L_L 512

#define MP 50048    // padded A rows (391*128)
#define NP 1024     // padded B rows (8*128)
#define KPAIR 152   // K in half-pairs: 304 halves = 19 chunks x 16
#define KU4 76      // uint4 per row

#define SCALE_IN  128.0f              // 2^7 per operand (keeps lo normal-range)
#define SCALE_OUT (1.0f / 16384.0f)   // 2^-14 on scores

// scratch — referenced ONLY from device code (never as host-side kernel args!)
__device__ float g_S[(size_t)M_V * N_F];        // 200 MB (scaled by 2^14)
__device__ uint2 g_A2[(size_t)MP * KPAIR];      // 61 MB pre-split (h2,l2)
__device__ uint2 g_B2[(size_t)NP * KPAIR];      // 1.2 MB

#define LDP 12                   // uint2 row stride (8 pairs + 4 pad) - proven
#define STAGE_U2 (256 * LDP)     // A rows 0..127, B rows 128..255 = 3072 uint2
#define NSTAGE 3
#define SMEM_BYTES (NSTAGE * STAGE_U2 * 8)   // 73728
#define NCHUNK 19

// ---------------------------------------------------------------------------
__device__ __forceinline__ uint32_t h2u(half2 h) {
    return *reinterpret_cast<const uint32_t*>(&h);
}

__device__ __forceinline__ void mma16(float* c, const uint32_t* a, const uint32_t* b) {
    asm volatile(
        "mma.sync.aligned.m16n8k16.row.col.f32.f16.f16.f32 "
        "{%0,%1,%2,%3}, {%4,%5,%6,%7}, {%8,%9}, {%0,%1,%2,%3};"
        : "+f"(c[0]), "+f"(c[1]), "+f"(c[2]), "+f"(c[3])
        : "r"(a[0]), "r"(a[1]), "r"(a[2]), "r"(a[3]), "r"(b[0]), "r"(b[1]));
}

#define CP16(sm_u32, gp) \
    asm volatile("cp.async.cg.shared.global [%0], [%1], 16;" :: "r"(sm_u32), "l"(gp))
#define CP_COMMIT() asm volatile("cp.async.commit_group;" ::: "memory")
#define CP_WAIT1()  asm volatile("cp.async.wait_group 1;" ::: "memory")

// split 4 floats (scaled 2^7) into two (hi2, lo2) uint2 pairs
__device__ __forceinline__ uint4 split4(float4 v) {
    float x0 = v.x * SCALE_IN, x1 = v.y * SCALE_IN;
    float x2 = v.z * SCALE_IN, x3 = v.w * SCALE_IN;
    half2 h01 = __floats2half2_rn(x0, x1);
    half2 h23 = __floats2half2_rn(x2, x3);
    float2 f01 = __half22float2(h01);
    float2 f23 = __half22float2(h23);
    half2 l01 = __floats2half2_rn(x0 - f01.x, x1 - f01.y);
    half2 l23 = __floats2half2_rn(x2 - f23.x, x3 - f23.y);
    return make_uint4(h2u(h01), h2u(l01), h2u(h23), h2u(l23));
}

// ===========================================================================
// Presplit: fp32 [rows x 300] -> pair-packed uint2 rows [KPAIR], value *2^7.
// uint2 q = (h2(x2q,x2q+1), l2(x2q,x2q+1)). Row/K padding zeroed.
// ===========================================================================
__global__ __launch_bounds__(256) void presplit_A(const float* __restrict__ src) {
    int idx = blockIdx.x * 256 + threadIdx.x;
    int row = idx / KU4, s = idx - row * KU4;
    if (row >= MP) return;
    float4 v = make_float4(0.f, 0.f, 0.f, 0.f);
    if (row < M_V && s < 75) v = *(const float4*)(src + (size_t)row * K_D + s * 4);
    *(uint4*)(g_A2 + (size_t)row * KPAIR + s * 2) = split4(v);
}

__global__ __launch_bounds__(256) void presplit_B(const float* __restrict__ src) {
    int idx = blockIdx.x * 256 + threadIdx.x;
    int row = idx / KU4, s = idx - row * KU4;
    if (row >= NP) return;
    float4 v = make_float4(0.f, 0.f, 0.f, 0.f);
    if (row < N_F && s < 75) v = *(const float4*)(src + (size_t)row * K_D + s * 4);
    *(uint4*)(g_B2 + (size_t)row * KPAIR + s * 2) = split4(v);
}

// ===========================================================================
// Phase 1: S = Ah.Bh + Ah.Bl + Al.Bh  via fp16 m16n8k16 mma.sync (NT)
// 128x128 CTA tile, BK=16 (19 chunks), 8 warps (64x32 warptile), LDP=12,
// cp.async staging, 2 CTAs/SM, THREE stages + wait_group 1:
// the chunk being computed was issued TWO iterations ago -> copy latency
// fully hidden (R15's wait_group 0 exposed the tail every chunk).
// ===========================================================================
__global__ __launch_bounds__(256, 2) void gemm_fp16x3() {
    extern __shared__ uint2 sm[];
    uint32_t smb;
    asm("{ .reg .u64 t; cvta.to.shared.u64 t, %1; cvt.u32.u64 %0, t; }"
        : "=r"(smb) : "l"(sm));

    const int tid = threadIdx.x;
    const int wid = tid >> 5, lid = tid & 31;
    const int qid = lid >> 2, ql = lid & 3;
    const int m0 = blockIdx.y * 128, n0 = blockIdx.x * 128;
    const int wm = (wid >> 2) * 64, wn = (wid & 3) * 32;

    float acc[4][4][4];
#pragma unroll
    for (int mt = 0; mt < 4; mt++)
#pragma unroll
        for (int nt = 0; nt < 4; nt++)
#pragma unroll
            for (int j = 0; j < 4; j++) acc[mt][nt][j] = 0.f;

    // staging: row = tid>>1 (0..127), half = tid&1 -> 2 uint4 of A + 2 of B
    const int row_st = tid >> 1, half = tid & 1;
    const uint4* gA = (const uint4*)(g_A2 + (size_t)(m0 + row_st) * KPAIR) + half * 2;
    const uint4* gB = (const uint4*)(g_B2 + (size_t)(n0 + row_st) * KPAIR) + half * 2;
    const uint32_t sAb = smb + (uint32_t)(row_st * LDP + half * 4) * 8;
    const uint32_t sBb = sAb + 128 * LDP * 8;

#define ISSUE(c, st) do { \
        uint32_t so = (uint32_t)(st) * (STAGE_U2 * 8); \
        const uint4* ga = gA + (c) * 4; \
        const uint4* gb = gB + (c) * 4; \
        CP16(sAb + so,      ga); CP16(sAb + so + 16, ga + 1); \
        CP16(sBb + so,      gb); CP16(sBb + so + 16, gb + 1); \
        CP_COMMIT(); \
    } while (0)

    // ---- prologue: chunks 0,1 into stages 0,1 ----
    ISSUE(0, 0);
    ISSUE(1, 1);

    int st = 0;                    // stage of chunk c
    for (int c = 0; c < NCHUNK; c++) {
        CP_WAIT1();                // chunk c landed (c+1 may be outstanding)
        __syncthreads();           // also retires compute of c-1 on all warps

        // issue c+2 into the stage last used by chunk c-1 (safe after barrier)
        if (c + 2 < NCHUNK) {
            int st2 = st + 2; if (st2 >= NSTAGE) st2 -= NSTAGE;
            ISSUE(c + 2, st2);
        } else {
            CP_COMMIT();           // empty group keeps wait_group 1 honest
        }

        const uint2* As = sm + st * STAGE_U2;
        const uint2* Bs = As + 128 * LDP;

        // ---- compute: one m16n8k16 per (mt,nt) per pass ----
        uint32_t bh[4][2], bl[4][2];
#pragma unroll
        for (int nt = 0; nt < 4; nt++) {
            const uint2* p = Bs + (wn + nt * 8 + qid) * LDP + ql;
            uint2 b0 = p[0], b1 = p[4];      // pairs ql, ql+4
            bh[nt][0] = b0.x; bh[nt][1] = b1.x;
            bl[nt][0] = b0.y; bl[nt][1] = b1.y;
        }
#pragma unroll
        for (int mt = 0; mt < 4; mt++) {
            const uint2* pa = As + (wm + mt * 16 + qid) * LDP + ql;
            uint2 a0 = pa[0], a1 = pa[8 * LDP];
            uint2 a2 = pa[4], a3 = pa[8 * LDP + 4];
            uint32_t ah[4] = {a0.x, a1.x, a2.x, a3.x};
            uint32_t al[4] = {a0.y, a1.y, a2.y, a3.y};
#pragma unroll
            for (int nt = 0; nt < 4; nt++) {
                mma16(acc[mt][nt], ah, bh[nt]);   // hi*hi
                mma16(acc[mt][nt], ah, bl[nt]);   // hi*lo
                mma16(acc[mt][nt], al, bh[nt]);   // lo*hi
            }
        }

        if (++st == NSTAGE) st = 0;
    }

    // ---- epilogue (scores scaled by 2^14; phase 2 descales) ----
#pragma unroll
    for (int mt = 0; mt < 4; mt++) {
        int mlo = m0 + wm + mt * 16 + qid;
        int mhi = mlo + 8;
#pragma unroll
        for (int nt = 0; nt < 4; nt++) {
            int n = n0 + wn + nt * 8 + ql * 2;
            if (n < N_F) {
                if (mlo < M_V)
                    *(float2*)(g_S + (size_t)mlo * N_F + n) =
                        make_float2(acc[mt][nt][0], acc[mt][nt][1]);
                if (mhi < M_V)
                    *(float2*)(g_S + (size_t)mhi * N_F + n) =
                        make_float2(acc[mt][nt][2], acc[mt][nt][3]);
            }
        }
    }
}

// ===========================================================================
// Phase 2: per (b,f): first-index argmax over t of S[inp[b,t],f] (scaled:
// argmax invariant); val = relu(2^-14*max + conv_b[f]);
// contrib = val*(fc_w[1,f]-fc_w[0,f]); token[b,argmax] += contrib;
// token += fc_b[1]-fc_b[0]. Deterministic ordered gather.
// ===========================================================================
__global__ __launch_bounds__(1024) void reduce_scatter(
    const int* __restrict__ inp, const float* __restrict__ cb,
    const float* __restrict__ fcw, const float* __restrict__ fcb,
    float* __restrict__ out) {
    __shared__ int   sw[L_L];
    __shared__ int   sbt[N_F];
    __shared__ float sct[N_F];

    const int b = blockIdx.x;
    const int tid = threadIdx.x;

    if (tid < L_L) sw[tid] = inp[b * L_L + tid];
    __syncthreads();

    const int f = tid;
    if (f < N_F) {
        const float* Sf = g_S + f;
        float best = -3.4e38f;
        int bestt = 0;
        for (int t0 = 0; t0 < L_L; t0 += 8) {
            float vv[8];
#pragma unroll
            for (int j = 0; j < 8; j++)
                vv[j] = Sf[(size_t)sw[t0 + j] * N_F];
#pragma unroll
            for (int j = 0; j < 8; j++) {
                if (vv[j] > best) { best = vv[j]; bestt = t0 + j; }  // first idx
            }
        }
        float val = fmaxf(best * SCALE_OUT + cb[f], 0.f);  // descale, relu
        float contrib = val * (fcw[N_F + f] - fcw[f]);     // 0 when val==0
        sbt[f] = bestt;
        sct[f] = contrib;
    }
    __syncthreads();

    if (tid < L_L) {
        float accv = fcb[1] - fcb[0];
        for (int ff = 0; ff < N_F; ff++) {
            if (sbt[ff] == tid) accv += sct[ff];
        }
        out[b * L_L + tid] = accv;
    }
}

extern "C" void kernel_launch(void* const* d_in, const int* in_sizes, int n_in,
                              void* d_out, int out_size) {
    const int*   inp    = (const int*)d_in[0];
    const float* emb    = (const float*)d_in[1];
    const float* conv_w = (const float*)d_in[2];   // [1000,1,300] contiguous
    const float* conv_b = (const float*)d_in[3];
    const float* fc_w   = (const float*)d_in[4];   // [2,1000]
    const float* fc_b   = (const float*)d_in[5];
    float* out = (float*)d_out;

    static int smem_set = 0;
    if (!smem_set) {
        cudaFuncSetAttribute(gemm_fp16x3,
                             cudaFuncAttributeMaxDynamicSharedMemorySize,
                             SMEM_BYTES);
        smem_set = 1;
    }

    presplit_A<<<(MP * KU4 + 255) / 256, 256>>>(emb);
    presplit_B<<<(NP * KU4 + 255) / 256, 256>>>(conv_w);
    gemm_fp16x3<<<dim3(8, 391), 256, SMEM_BYTES>>>();
    reduce_scatter<<<B_B, 1024>>>(inp, conv_b, fc_w, fc_b, out);
}